// round 3
// baseline (speedup 1.0000x reference)
#include <cuda_runtime.h>
#include <cuda_bf16.h>
#include <math.h>
#include <stdint.h>

// Problem constants
#define BATCH 4
#define CDIM  384
#define HEADS 8
#define CH    48          // channels per head
#define HH    128
#define WW    128
#define HW    16384       // HH*WW

// ---------------------------------------------------------------------------
// Scratch buffers (device globals; no allocation allowed)
// ---------------------------------------------------------------------------
__device__ float g_tmp[(size_t)BATCH * CDIM * HW];          // pw output before dw
__device__ float g_cat[(size_t)BATCH * 2 * CDIM * HW];      // [q_dw ; qT_dw] per batch
__device__ float g_k  [(size_t)BATCH * CDIM * HW];
__device__ float g_v  [(size_t)BATCH * CDIM * HW];
__device__ float g_q  [(size_t)BATCH * CDIM * HW];
__device__ float g_attn[(size_t)BATCH * HEADS * CH * CH];
__device__ float g_invq[BATCH * CDIM];
__device__ float g_nk[BATCH * CDIM];     // sum-of-squares accumulator for k

// ---------------------------------------------------------------------------
// TF32 tensor-core GEMM: C[b] = A (MxK row-major) @ B[b] (KxN row-major)
// BM=128, BN=128, BK=16; 256 threads; warp tile 64x32 via m16n8k8 tf32 mma.
// Two-deep register staging to cover DRAM latency.
// ---------------------------------------------------------------------------
#define BM 128
#define BN 128
#define BK 16
#define SSTRIDE 136   // padded row stride (floats) for conflict-free frag loads

__device__ __forceinline__ uint32_t f2tf32(float x) {
    uint32_t r;
    asm("cvt.rna.tf32.f32 %0, %1;" : "=r"(r) : "f"(x));
    return r;
}

__device__ __forceinline__ void mma_tf32(float* c, const uint32_t* a, const uint32_t* b) {
    asm volatile(
        "mma.sync.aligned.m16n8k8.row.col.f32.tf32.tf32.f32 "
        "{%0,%1,%2,%3}, {%4,%5,%6,%7}, {%8,%9}, {%0,%1,%2,%3};\n"
        : "+f"(c[0]), "+f"(c[1]), "+f"(c[2]), "+f"(c[3])
        : "r"(a[0]), "r"(a[1]), "r"(a[2]), "r"(a[3]), "r"(b[0]), "r"(b[1]));
}

__global__ __launch_bounds__(256, 1)
void tgemm_kernel(const float* __restrict__ A, const float* __restrict__ Bb,
                  float* __restrict__ Cb, int M, int N, int K)
{
    const int bz = blockIdx.z;
    const float* B = Bb + (size_t)bz * K * N;
    float*       C = Cb + (size_t)bz * M * N;

    __shared__ uint32_t As[2][BK][SSTRIDE];   // [k][m], tf32 bits
    __shared__ uint32_t Bs[2][BK][SSTRIDE];   // [k][n], tf32 bits

    const int tid  = threadIdx.x;
    const int lane = tid & 31, warp = tid >> 5;
    const int g = lane >> 2, tig = lane & 3;
    const int wm = (warp >> 2) * 64;          // warp M offset (0/64)
    const int wn = (warp & 3) * 32;           // warp N offset (0/32/64/96)
    const int brow = blockIdx.y * BM;
    const int bcol = blockIdx.x * BN;

    const int am  = tid & 127;
    const int akc = (tid >> 7) * 4;           // 0 or 4; second element adds 8
    const int bkr = tid >> 5;                 // 0..7; second element adds 8
    const int bnc = (tid & 31) * 4;

    const float* Aptr = A + (size_t)(brow + am) * K;
    const float* Bptr = B + bcol + bnc;

    float acc[4][4][4];
#pragma unroll
    for (int i = 0; i < 4; i++)
#pragma unroll
        for (int j = 0; j < 4; j++)
#pragma unroll
            for (int r = 0; r < 4; r++) acc[i][j][r] = 0.f;

    const int iters = K / BK;                 // >= 24 always here

    // two register staging sets
    float4 sa0[2], sa1[2], sb0[2], sb1[2];

#define LOADSET(s_, J_)                                                      \
    do {                                                                     \
        const float* Ap_ = Aptr + (J_)*BK;                                   \
        const float* Bp_ = Bptr + (size_t)((J_)*BK) * N;                     \
        sa0[s_] = *(const float4*)(Ap_ + akc);                               \
        sa1[s_] = *(const float4*)(Ap_ + akc + 8);                           \
        sb0[s_] = *(const float4*)(Bp_ + (size_t)bkr * N);                   \
        sb1[s_] = *(const float4*)(Bp_ + (size_t)(bkr + 8) * N);             \
    } while (0)

#define STASH(s_, buf_)                                                      \
    do {                                                                     \
        As[buf_][akc + 0][am] = f2tf32(sa0[s_].x);                           \
        As[buf_][akc + 1][am] = f2tf32(sa0[s_].y);                           \
        As[buf_][akc + 2][am] = f2tf32(sa0[s_].z);                           \
        As[buf_][akc + 3][am] = f2tf32(sa0[s_].w);                           \
        As[buf_][akc + 8][am] = f2tf32(sa1[s_].x);                           \
        As[buf_][akc + 9][am] = f2tf32(sa1[s_].y);                           \
        As[buf_][akc +10][am] = f2tf32(sa1[s_].z);                           \
        As[buf_][akc +11][am] = f2tf32(sa1[s_].w);                           \
        uint4 p0 = make_uint4(f2tf32(sb0[s_].x), f2tf32(sb0[s_].y),          \
                              f2tf32(sb0[s_].z), f2tf32(sb0[s_].w));         \
        uint4 p1 = make_uint4(f2tf32(sb1[s_].x), f2tf32(sb1[s_].y),          \
                              f2tf32(sb1[s_].z), f2tf32(sb1[s_].w));         \
        *(uint4*)&Bs[buf_][bkr][bnc]     = p0;                               \
        *(uint4*)&Bs[buf_][bkr + 8][bnc] = p1;                               \
    } while (0)

    LOADSET(0, 0);
    LOADSET(1, 1);
    STASH(0, 0);
    __syncthreads();
    LOADSET(0, 2);
    int buf = 0;

    for (int it = 0; it < iters; ++it) {
#pragma unroll
        for (int kk = 0; kk < BK; kk += 8) {
            uint32_t af[4][4], bf[4][2];
#pragma unroll
            for (int i = 0; i < 4; i++) {
                const int mr = wm + i * 16 + g;
                af[i][0] = As[buf][kk + tig    ][mr];
                af[i][1] = As[buf][kk + tig    ][mr + 8];
                af[i][2] = As[buf][kk + tig + 4][mr];
                af[i][3] = As[buf][kk + tig + 4][mr + 8];
            }
#pragma unroll
            for (int j = 0; j < 4; j++) {
                const int nr = wn + j * 8 + g;
                bf[j][0] = Bs[buf][kk + tig    ][nr];
                bf[j][1] = Bs[buf][kk + tig + 4][nr];
            }
#pragma unroll
            for (int i = 0; i < 4; i++)
#pragma unroll
                for (int j = 0; j < 4; j++)
                    mma_tf32(acc[i][j], af[i], bf[j]);
        }

        const int nxt = it + 1;
        if (nxt < iters) {
            STASH(nxt & 1, buf ^ 1);
            __syncthreads();
            buf ^= 1;
            if (it + 3 < iters) LOADSET(nxt & 1, it + 3);
        }
    }
#undef LOADSET
#undef STASH

#pragma unroll
    for (int i = 0; i < 4; i++) {
        const int r0 = brow + wm + i * 16 + g;
#pragma unroll
        for (int j = 0; j < 4; j++) {
            const int cc = bcol + wn + j * 8 + 2 * tig;
            *(float2*)&C[(size_t)r0 * N + cc]       = make_float2(acc[i][j][0], acc[i][j][1]);
            *(float2*)&C[(size_t)(r0 + 8) * N + cc] = make_float2(acc[i][j][2], acc[i][j][3]);
        }
    }
}

// ---------------------------------------------------------------------------
// Depthwise 3x3 SAME conv, vectorized: 16 rows x 128 cols per block,
// 4 outputs/thread via float4. Optional fused sum-of-squares accumulation.
// ---------------------------------------------------------------------------
#define DTY 16
__global__ __launch_bounds__(256)
void dw3x3_kernel(const float* __restrict__ in, const float* __restrict__ w,
                  float* __restrict__ out,
                  size_t inBatchStride, size_t outBatchStride, int outChanOff,
                  float* __restrict__ nrm)
{
    const int c = blockIdx.y;
    const int b = blockIdx.z;
    const int y0 = blockIdx.x * DTY;
    const float* ip = in + (size_t)b * inBatchStride + (size_t)c * HW;
    float*       op = out + (size_t)b * outBatchStride + (size_t)(c + outChanOff) * HW;
    const float* wc = w + c * 9;

    // data at sm[r][4 + x], x in [-1, 128]; float4-aligned at 4+4q
    __shared__ float sm[DTY + 2][136];

    const int tid = threadIdx.x;
    const float4 z4 = make_float4(0.f, 0.f, 0.f, 0.f);
    // 18 rows x 34 slots (32 float4 + 2 halo scalars)
    for (int s = tid; s < (DTY + 2) * 34; s += 256) {
        const int r = s / 34;
        const int q = s - r * 34;
        const int gy = y0 - 1 + r;
        if (q < 32) {
            float4 v = (gy >= 0 && gy < HH) ? *(const float4*)(ip + gy * WW + q * 4) : z4;
            *(float4*)&sm[r][4 + q * 4] = v;
        } else if (q == 32) {
            sm[r][3] = 0.f;           // x = -1
        } else {
            sm[r][4 + WW] = 0.f;      // x = 128
        }
    }
    __syncthreads();

    const float w00 = wc[0], w01 = wc[1], w02 = wc[2];
    const float w10 = wc[3], w11 = wc[4], w12 = wc[5];
    const float w20 = wc[6], w21 = wc[7], w22 = wc[8];

    float s2 = 0.f;
#pragma unroll
    for (int i = 0; i < (DTY * 32) / 256; i++) {       // 2 iterations
        const int oid = tid + i * 256;
        const int y = oid >> 5;            // 0..15
        const int xq = oid & 31;           // float4 index
        float o0 = 0.f, o1 = 0.f, o2 = 0.f, o3 = 0.f;
#pragma unroll
        for (int r = 0; r < 3; r++) {
            const float wr0 = (r == 0) ? w00 : (r == 1) ? w10 : w20;
            const float wr1 = (r == 0) ? w01 : (r == 1) ? w11 : w21;
            const float wr2 = (r == 0) ? w02 : (r == 1) ? w12 : w22;
            const float4 cc = *(const float4*)&sm[y + r][4 + xq * 4];
            const float l  = sm[y + r][3 + xq * 4];
            const float rr = sm[y + r][8 + xq * 4];
            o0 += l    * wr0 + cc.x * wr1 + cc.y * wr2;
            o1 += cc.x * wr0 + cc.y * wr1 + cc.z * wr2;
            o2 += cc.y * wr0 + cc.z * wr1 + cc.w * wr2;
            o3 += cc.z * wr0 + cc.w * wr1 + rr   * wr2;
        }
        *(float4*)(op + (y0 + y) * WW + xq * 4) = make_float4(o0, o1, o2, o3);
        s2 += o0 * o0 + o1 * o1 + o2 * o2 + o3 * o3;
    }

    if (nrm) {
#pragma unroll
        for (int off = 16; off > 0; off >>= 1)
            s2 += __shfl_xor_sync(0xffffffff, s2, off);
        __shared__ float wred[8];
        if ((tid & 31) == 0) wred[tid >> 5] = s2;
        __syncthreads();
        if (tid == 0) {
            float tot = 0.f;
#pragma unroll
            for (int ww2 = 0; ww2 < 8; ww2++) tot += wred[ww2];
            atomicAdd(&nrm[b * CDIM + c], tot);
        }
    }
}

// ---------------------------------------------------------------------------
// Row L2 inverse norm over HW:  inv[r] = 1 / max(||row||_2, 1e-12)
// ---------------------------------------------------------------------------
__global__ void rownorm_kernel(const float* __restrict__ in, float* __restrict__ inv)
{
    const int r = blockIdx.x;                 // 0 .. BATCH*CDIM-1
    const float* p = in + (size_t)r * HW;
    float s = 0.f;
    for (int i = threadIdx.x; i < HW / 4; i += blockDim.x) {
        float4 v = ((const float4*)p)[i];
        s += v.x * v.x + v.y * v.y + v.z * v.z + v.w * v.w;
    }
    __shared__ float red[256];
    red[threadIdx.x] = s;
    __syncthreads();
    for (int off = 128; off > 0; off >>= 1) {
        if (threadIdx.x < off) red[threadIdx.x] += red[threadIdx.x + off];
        __syncthreads();
    }
    if (threadIdx.x == 0)
        inv[r] = 1.f / fmaxf(sqrtf(red[0]), 1e-12f);
}

// ---------------------------------------------------------------------------
// Zero attention accumulator + k-norm accumulator
// ---------------------------------------------------------------------------
__global__ void zero_kernel()
{
    int i = blockIdx.x * blockDim.x + threadIdx.x;
    if (i < BATCH * HEADS * CH * CH) g_attn[i] = 0.f;
    if (i < BATCH * CDIM) g_nk[i] = 0.f;
}

// ---------------------------------------------------------------------------
// attn_raw[bh][c][d] += sum_n q[c][n]*k[d][n]   (split over N, atomic reduce)
// ---------------------------------------------------------------------------
#define NSPLIT 16
__global__ void attn_score_kernel(const float* __restrict__ q, const float* __restrict__ k)
{
    const int bh = blockIdx.x;                     // 0..31
    const int sp = blockIdx.y;                     // 0..NSPLIT-1
    const int b = bh >> 3, h = bh & 7;
    const float* qp = q + ((size_t)b * CDIM + h * CH) * HW;
    const float* kp = k + ((size_t)b * CDIM + h * CH) * HW;

    __shared__ float qs[CH][36];
    __shared__ float ks[CH][36];

    const int tid = threadIdx.x;                   // 256
    const int tx = tid % 16, ty = tid / 16;
    const int c0 = ty * 3, d0 = tx * 3;

    float acc[3][3] = {{0.f}};
    const int perSplit = HW / NSPLIT;              // 1024
    const int base = sp * perSplit;

    for (int t0 = 0; t0 < perSplit; t0 += 32) {
        // stage 48 rows x 32 cols as float4
        for (int i = tid; i < CH * 8; i += 256) {
            int cc = i >> 3, kq = i & 7;
            float4 vq = *(const float4*)(qp + (size_t)cc * HW + base + t0 + kq * 4);
            float4 vk = *(const float4*)(kp + (size_t)cc * HW + base + t0 + kq * 4);
            *(float4*)&qs[cc][kq * 4] = vq;
            *(float4*)&ks[cc][kq * 4] = vk;
        }
        __syncthreads();
#pragma unroll
        for (int kk = 0; kk < 32; kk++) {
            float a0 = qs[c0 + 0][kk], a1 = qs[c0 + 1][kk], a2 = qs[c0 + 2][kk];
            float e0 = ks[d0 + 0][kk], e1 = ks[d0 + 1][kk], e2 = ks[d0 + 2][kk];
            acc[0][0] += a0 * e0; acc[0][1] += a0 * e1; acc[0][2] += a0 * e2;
            acc[1][0] += a1 * e0; acc[1][1] += a1 * e1; acc[1][2] += a1 * e2;
            acc[2][0] += a2 * e0; acc[2][1] += a2 * e1; acc[2][2] += a2 * e2;
        }
        __syncthreads();
    }

    float* ap = g_attn + (size_t)bh * CH * CH;
#pragma unroll
    for (int i = 0; i < 3; i++)
#pragma unroll
        for (int j = 0; j < 3; j++)
            atomicAdd(&ap[(c0 + i) * CH + d0 + j], acc[i][j]);
}

// ---------------------------------------------------------------------------
// Softmax with norm scaling + temperature, in place on g_attn.
// invq holds 1/||q||; nk holds raw sum-of-squares for k.
// One warp per (bh, c) row.
// ---------------------------------------------------------------------------
__global__ void softmax_kernel(const float* __restrict__ invq, const float* __restrict__ nk,
                               const float* __restrict__ temp)
{
    const int r = blockIdx.x;                      // 0 .. 32*48-1
    const int bh = r / CH, c = r % CH;
    const int b = bh >> 3, h = bh & 7;
    const int lane = threadIdx.x;                  // 32

    float* row = g_attn + (size_t)bh * CH * CH + (size_t)c * CH;
    const float iq = invq[b * CDIM + h * CH + c];
    const float tp = temp[h];

    const float ik0 = 1.f / fmaxf(sqrtf(nk[b * CDIM + h * CH + lane]), 1e-12f);
    float l0 = row[lane] * iq * ik0 * tp;
    float l1 = -INFINITY;
    if (lane < CH - 32) {
        const float ik1 = 1.f / fmaxf(sqrtf(nk[b * CDIM + h * CH + lane + 32]), 1e-12f);
        l1 = row[lane + 32] * iq * ik1 * tp;
    }

    float m = fmaxf(l0, l1);
#pragma unroll
    for (int off = 16; off > 0; off >>= 1)
        m = fmaxf(m, __shfl_xor_sync(0xffffffff, m, off));

    float e0 = expf(l0 - m);
    float e1 = (lane < CH - 32) ? expf(l1 - m) : 0.f;
    float s = e0 + e1;
#pragma unroll
    for (int off = 16; off > 0; off >>= 1)
        s += __shfl_xor_sync(0xffffffff, s, off);

    float rs = 1.f / s;
    row[lane] = e0 * rs;
    if (lane < CH - 32) row[lane + 32] = e1 * rs;
}

// ---------------------------------------------------------------------------
// out[bh][c][p] = sum_d attn[bh][c][d] * v[bh][d][p]
// ---------------------------------------------------------------------------
__global__ __launch_bounds__(128)
void attn_out_kernel(const float* __restrict__ v, float* __restrict__ out)
{
    const int bh = blockIdx.y;
    const int b = bh >> 3, h = bh & 7;
    const int p = blockIdx.x * blockDim.x + threadIdx.x;

    __shared__ float as[CH][CH];
    for (int i = threadIdx.x; i < CH * CH; i += blockDim.x)
        as[i / CH][i % CH] = g_attn[(size_t)bh * CH * CH + i];
    __syncthreads();

    const float* vp = v + ((size_t)b * CDIM + h * CH) * HW;
    float*       op = out + ((size_t)b * CDIM + h * CH) * HW;

    float vr[CH];
#pragma unroll
    for (int d = 0; d < CH; d++) vr[d] = vp[(size_t)d * HW + p];

#pragma unroll
    for (int c = 0; c < CH; c++) {
        float s = 0.f;
#pragma unroll
        for (int d = 0; d < CH; d++) s += as[c][d] * vr[d];
        op[(size_t)c * HW + p] = s;
    }
}

// ---------------------------------------------------------------------------
// Host launcher
// ---------------------------------------------------------------------------
extern "C" void kernel_launch(void* const* d_in, const int* in_sizes, int n_in,
                              void* d_out, int out_size)
{
    const float* x      = (const float*)d_in[0];
    const float* t      = (const float*)d_in[1];
    const float* w_q    = (const float*)d_in[2];
    const float* w_q_dw = (const float*)d_in[3];
    const float* w_qT   = (const float*)d_in[4];
    const float* w_qT_dw= (const float*)d_in[5];
    const float* w_qcat = (const float*)d_in[6];
    const float* w_k    = (const float*)d_in[7];
    const float* w_k_dw = (const float*)d_in[8];
    const float* w_v    = (const float*)d_in[9];
    const float* w_v_dw = (const float*)d_in[10];
    const float* temp   = (const float*)d_in[11];
    float* out = (float*)d_out;

    float *p_tmp, *p_cat, *p_k, *p_v, *p_q, *p_invq, *p_nk;
    cudaGetSymbolAddress((void**)&p_tmp, g_tmp);
    cudaGetSymbolAddress((void**)&p_cat, g_cat);
    cudaGetSymbolAddress((void**)&p_k,   g_k);
    cudaGetSymbolAddress((void**)&p_v,   g_v);
    cudaGetSymbolAddress((void**)&p_q,   g_q);
    cudaGetSymbolAddress((void**)&p_invq, g_invq);
    cudaGetSymbolAddress((void**)&p_nk,  g_nk);

    const dim3 gemmGrid(HW / BN, CDIM / BM, BATCH);   // 128 x 3 x 4
    const dim3 dwGrid(HH / DTY, CDIM, BATCH);         // 8 x 384 x 4
    const size_t bsIn  = (size_t)CDIM * HW;
    const size_t bsCat = (size_t)2 * CDIM * HW;

    // zero accumulators (attn + k-norm)
    zero_kernel<<<(BATCH * HEADS * CH * CH + 255) / 256, 256>>>();

    // q branch: pw(x, w_q) -> dw -> g_cat[:, 0:384]
    tgemm_kernel<<<gemmGrid, 256>>>(w_q, x, p_tmp, CDIM, HW, CDIM);
    dw3x3_kernel<<<dwGrid, 256>>>(p_tmp, w_q_dw, p_cat, bsIn, bsCat, 0, nullptr);

    // qT branch: pw(t, w_qT) -> dw -> g_cat[:, 384:768]
    tgemm_kernel<<<gemmGrid, 256>>>(w_qT, t, p_tmp, CDIM, HW, CDIM);
    dw3x3_kernel<<<dwGrid, 256>>>(p_tmp, w_qT_dw, p_cat, bsIn, bsCat, CDIM, nullptr);

    // k branch (fused sum-of-squares accumulation)
    tgemm_kernel<<<gemmGrid, 256>>>(w_k, x, p_tmp, CDIM, HW, CDIM);
    dw3x3_kernel<<<dwGrid, 256>>>(p_tmp, w_k_dw, p_k, bsIn, bsIn, 0, p_nk);

    // v branch
    tgemm_kernel<<<gemmGrid, 256>>>(w_v, x, p_tmp, CDIM, HW, CDIM);
    dw3x3_kernel<<<dwGrid, 256>>>(p_tmp, w_v_dw, p_v, bsIn, bsIn, 0, nullptr);

    // q = pw(concat, w_qcat): K = 768
    tgemm_kernel<<<gemmGrid, 256>>>(w_qcat, p_cat, p_q, CDIM, HW, 2 * CDIM);

    // L2 norm for q (k norm fused into dw above)
    rownorm_kernel<<<BATCH * CDIM, 256>>>(p_q, p_invq);

    // attention scores
    attn_score_kernel<<<dim3(BATCH * HEADS, NSPLIT), 256>>>(p_q, p_k);
    softmax_kernel<<<BATCH * HEADS * CH, 32>>>(p_invq, p_nk, temp);

    // output
    attn_out_kernel<<<dim3(HW / 128, BATCH * HEADS), 128>>>(p_v, out);
}

// round 4
// speedup vs baseline: 1.5807x; 1.5807x over previous
#include <cuda_runtime.h>
#include <cuda_bf16.h>
#include <math.h>
#include <stdint.h>

// Problem constants
#define BATCH 4
#define CDIM  384
#define HEADS 8
#define CH    48          // channels per head
#define HH    128
#define WW    128
#define HW    16384       // HH*WW

// ---------------------------------------------------------------------------
// Scratch buffers (device globals; no allocation allowed)
// ---------------------------------------------------------------------------
__device__ float g_tmp[(size_t)BATCH * CDIM * HW];
__device__ float g_cat[(size_t)BATCH * 2 * CDIM * HW];
__device__ float g_k  [(size_t)BATCH * CDIM * HW];
__device__ float g_v  [(size_t)BATCH * CDIM * HW];
__device__ float g_q  [(size_t)BATCH * CDIM * HW];
__device__ float g_attn[(size_t)BATCH * HEADS * CH * CH];
__device__ float g_invq[BATCH * CDIM];
__device__ float g_nk[BATCH * CDIM];

// ---------------------------------------------------------------------------
// TF32 tensor-core GEMM with 4-stage cp.async pipeline.
// C[b] = A (MxK row-major) @ B[b] (KxN row-major)
// BM=128, BN=128, BK=16; 256 threads; warp tile 64x32 via m16n8k8 tf32 mma.
// blockIdx.x = M tile (3), blockIdx.y = N tile (128) for B-panel L2 reuse.
// ---------------------------------------------------------------------------
#define BM 128
#define BN 128
#define BK 16
#define STAGES 4
#define ASTRIDE 20       // A smem row stride (floats): conflict-free frag loads
#define BSTRIDE 136      // B smem row stride
#define A_STAGE (BM * ASTRIDE)            // 2560 floats
#define B_STAGE (BK * BSTRIDE)            // 2176 floats
#define SMEM_FLOATS (STAGES * (A_STAGE + B_STAGE))

__device__ __forceinline__ uint32_t f2tf32(float x) {
    uint32_t r;
    asm("cvt.rna.tf32.f32 %0, %1;" : "=r"(r) : "f"(x));
    return r;
}

__device__ __forceinline__ void mma_tf32(float* c, const uint32_t* a, const uint32_t* b) {
    asm volatile(
        "mma.sync.aligned.m16n8k8.row.col.f32.tf32.tf32.f32 "
        "{%0,%1,%2,%3}, {%4,%5,%6,%7}, {%8,%9}, {%0,%1,%2,%3};\n"
        : "+f"(c[0]), "+f"(c[1]), "+f"(c[2]), "+f"(c[3])
        : "r"(a[0]), "r"(a[1]), "r"(a[2]), "r"(a[3]), "r"(b[0]), "r"(b[1]));
}

__device__ __forceinline__ void cp16(uint32_t smem_addr, const void* gptr) {
    asm volatile("cp.async.cg.shared.global [%0], [%1], 16;\n"
                 :: "r"(smem_addr), "l"(gptr));
}

__global__ __launch_bounds__(256, 2)
void tgemm_kernel(const float* __restrict__ A, const float* __restrict__ Bb,
                  float* __restrict__ Cb, int M, int N, int K)
{
    const int bz = blockIdx.z;
    const float* B = Bb + (size_t)bz * K * N;
    float*       C = Cb + (size_t)bz * M * N;

    extern __shared__ float smem[];
    float* Asm = smem;                       // [STAGES][BM][ASTRIDE]
    float* Bsm = smem + STAGES * A_STAGE;    // [STAGES][BK][BSTRIDE]

    const int tid  = threadIdx.x;
    const int lane = tid & 31, warp = tid >> 5;
    const int g = lane >> 2, tig = lane & 3;
    const int wm = (warp >> 2) * 64;
    const int wn = (warp & 3) * 32;
    const int brow = blockIdx.x * BM;
    const int bcol = blockIdx.y * BN;

    // cp.async thread mapping
    const int am  = tid & 127;               // A row
    const int aq0 = (tid >> 7) * 2;          // A quad base (2 quads/thread)
    const int bkk = tid >> 4;                // B k row
    const int bq0 = (tid & 15) * 2;          // B quad base (2 quads/thread)

    const float* Abase = A + (size_t)(brow + am) * K;
    const float* Bbase = B + bcol;

    const uint32_t sA = (uint32_t)__cvta_generic_to_shared(Asm);
    const uint32_t sB = (uint32_t)__cvta_generic_to_shared(Bsm);

    const int iters = K / BK;

#define ISSUE(stage_, J_)                                                     \
    do {                                                                      \
        const int s_ = (stage_);                                              \
        const float* Ap_ = Abase + (J_)*BK;                                   \
        const float* Bp_ = Bbase + (size_t)((J_)*BK) * N;                     \
        cp16(sA + (s_ * A_STAGE + am * ASTRIDE + aq0 * 4) * 4, Ap_ + aq0 * 4);\
        cp16(sA + (s_ * A_STAGE + am * ASTRIDE + (aq0 + 1) * 4) * 4,          \
             Ap_ + (aq0 + 1) * 4);                                            \
        cp16(sB + (s_ * B_STAGE + bkk * BSTRIDE + bq0 * 4) * 4,               \
             Bp_ + (size_t)bkk * N + bq0 * 4);                                \
        cp16(sB + (s_ * B_STAGE + bkk * BSTRIDE + (bq0 + 1) * 4) * 4,         \
             Bp_ + (size_t)bkk * N + (bq0 + 1) * 4);                          \
    } while (0)

    // prologue: STAGES-1 stages in flight
#pragma unroll
    for (int s = 0; s < STAGES - 1; s++) {
        ISSUE(s, s);
        asm volatile("cp.async.commit_group;\n" ::: "memory");
    }

    float acc[4][4][4];
#pragma unroll
    for (int i = 0; i < 4; i++)
#pragma unroll
        for (int j = 0; j < 4; j++)
#pragma unroll
            for (int r = 0; r < 4; r++) acc[i][j][r] = 0.f;

    int buf = 0;
    for (int it = 0; it < iters; ++it) {
        asm volatile("cp.async.wait_group %0;\n" :: "n"(STAGES - 2) : "memory");
        __syncthreads();

        const float* Ab = Asm + buf * A_STAGE;
        const float* Bs = Bsm + buf * B_STAGE;

#pragma unroll
        for (int kk = 0; kk < BK; kk += 8) {
            uint32_t af[4][4], bf[4][2];
#pragma unroll
            for (int i = 0; i < 4; i++) {
                const int mr = wm + i * 16 + g;
                af[i][0] = f2tf32(Ab[mr * ASTRIDE + kk + tig]);
                af[i][1] = f2tf32(Ab[(mr + 8) * ASTRIDE + kk + tig]);
                af[i][2] = f2tf32(Ab[mr * ASTRIDE + kk + tig + 4]);
                af[i][3] = f2tf32(Ab[(mr + 8) * ASTRIDE + kk + tig + 4]);
            }
#pragma unroll
            for (int j = 0; j < 4; j++) {
                const int nr = wn + j * 8 + g;
                bf[j][0] = f2tf32(Bs[(kk + tig) * BSTRIDE + nr]);
                bf[j][1] = f2tf32(Bs[(kk + tig + 4) * BSTRIDE + nr]);
            }
#pragma unroll
            for (int i = 0; i < 4; i++)
#pragma unroll
                for (int j = 0; j < 4; j++)
                    mma_tf32(acc[i][j], af[i], bf[j]);
        }

        // issue copy for stage it+STAGES-1 into the buffer freed last iteration
        const int nj = it + STAGES - 1;
        if (nj < iters) {
            ISSUE(nj & (STAGES - 1), nj);
        }
        asm volatile("cp.async.commit_group;\n" ::: "memory");
        buf = (buf + 1) & (STAGES - 1);
    }
#undef ISSUE

#pragma unroll
    for (int i = 0; i < 4; i++) {
        const int r0 = brow + wm + i * 16 + g;
#pragma unroll
        for (int j = 0; j < 4; j++) {
            const int cc = bcol + wn + j * 8 + 2 * tig;
            *(float2*)&C[(size_t)r0 * N + cc]       = make_float2(acc[i][j][0], acc[i][j][1]);
            *(float2*)&C[(size_t)(r0 + 8) * N + cc] = make_float2(acc[i][j][2], acc[i][j][3]);
        }
    }
}

// ---------------------------------------------------------------------------
// Depthwise 3x3 SAME conv, vectorized: 16 rows x 128 cols per block,
// 4 outputs/thread via float4. Optional fused sum-of-squares accumulation.
// ---------------------------------------------------------------------------
#define DTY 16
__global__ __launch_bounds__(256)
void dw3x3_kernel(const float* __restrict__ in, const float* __restrict__ w,
                  float* __restrict__ out,
                  size_t inBatchStride, size_t outBatchStride, int outChanOff,
                  float* __restrict__ nrm)
{
    const int c = blockIdx.y;
    const int b = blockIdx.z;
    const int y0 = blockIdx.x * DTY;
    const float* ip = in + (size_t)b * inBatchStride + (size_t)c * HW;
    float*       op = out + (size_t)b * outBatchStride + (size_t)(c + outChanOff) * HW;
    const float* wc = w + c * 9;

    __shared__ float sm[DTY + 2][136];

    const int tid = threadIdx.x;
    const float4 z4 = make_float4(0.f, 0.f, 0.f, 0.f);
    for (int s = tid; s < (DTY + 2) * 34; s += 256) {
        const int r = s / 34;
        const int q = s - r * 34;
        const int gy = y0 - 1 + r;
        if (q < 32) {
            float4 v = (gy >= 0 && gy < HH) ? *(const float4*)(ip + gy * WW + q * 4) : z4;
            *(float4*)&sm[r][4 + q * 4] = v;
        } else if (q == 32) {
            sm[r][3] = 0.f;
        } else {
            sm[r][4 + WW] = 0.f;
        }
    }
    __syncthreads();

    const float w00 = wc[0], w01 = wc[1], w02 = wc[2];
    const float w10 = wc[3], w11 = wc[4], w12 = wc[5];
    const float w20 = wc[6], w21 = wc[7], w22 = wc[8];

    float s2 = 0.f;
#pragma unroll
    for (int i = 0; i < (DTY * 32) / 256; i++) {
        const int oid = tid + i * 256;
        const int y = oid >> 5;
        const int xq = oid & 31;
        float o0 = 0.f, o1 = 0.f, o2 = 0.f, o3 = 0.f;
#pragma unroll
        for (int r = 0; r < 3; r++) {
            const float wr0 = (r == 0) ? w00 : (r == 1) ? w10 : w20;
            const float wr1 = (r == 0) ? w01 : (r == 1) ? w11 : w21;
            const float wr2 = (r == 0) ? w02 : (r == 1) ? w12 : w22;
            const float4 cc = *(const float4*)&sm[y + r][4 + xq * 4];
            const float l  = sm[y + r][3 + xq * 4];
            const float rr = sm[y + r][8 + xq * 4];
            o0 += l    * wr0 + cc.x * wr1 + cc.y * wr2;
            o1 += cc.x * wr0 + cc.y * wr1 + cc.z * wr2;
            o2 += cc.y * wr0 + cc.z * wr1 + cc.w * wr2;
            o3 += cc.z * wr0 + cc.w * wr1 + rr   * wr2;
        }
        *(float4*)(op + (y0 + y) * WW + xq * 4) = make_float4(o0, o1, o2, o3);
        s2 += o0 * o0 + o1 * o1 + o2 * o2 + o3 * o3;
    }

    if (nrm) {
#pragma unroll
        for (int off = 16; off > 0; off >>= 1)
            s2 += __shfl_xor_sync(0xffffffff, s2, off);
        __shared__ float wred[8];
        if ((tid & 31) == 0) wred[tid >> 5] = s2;
        __syncthreads();
        if (tid == 0) {
            float tot = 0.f;
#pragma unroll
            for (int ww2 = 0; ww2 < 8; ww2++) tot += wred[ww2];
            atomicAdd(&nrm[b * CDIM + c], tot);
        }
    }
}

// ---------------------------------------------------------------------------
// Row L2 inverse norm over HW
// ---------------------------------------------------------------------------
__global__ void rownorm_kernel(const float* __restrict__ in, float* __restrict__ inv)
{
    const int r = blockIdx.x;
    const float* p = in + (size_t)r * HW;
    float s = 0.f;
    for (int i = threadIdx.x; i < HW / 4; i += blockDim.x) {
        float4 v = ((const float4*)p)[i];
        s += v.x * v.x + v.y * v.y + v.z * v.z + v.w * v.w;
    }
    __shared__ float red[256];
    red[threadIdx.x] = s;
    __syncthreads();
    for (int off = 128; off > 0; off >>= 1) {
        if (threadIdx.x < off) red[threadIdx.x] += red[threadIdx.x + off];
        __syncthreads();
    }
    if (threadIdx.x == 0)
        inv[r] = 1.f / fmaxf(sqrtf(red[0]), 1e-12f);
}

__global__ void zero_kernel()
{
    int i = blockIdx.x * blockDim.x + threadIdx.x;
    if (i < BATCH * HEADS * CH * CH) g_attn[i] = 0.f;
    if (i < BATCH * CDIM) g_nk[i] = 0.f;
}

// ---------------------------------------------------------------------------
// attn_raw[bh][c][d] += sum_n q[c][n]*k[d][n]
// ---------------------------------------------------------------------------
#define NSPLIT 16
__global__ void attn_score_kernel(const float* __restrict__ q, const float* __restrict__ k)
{
    const int bh = blockIdx.x;
    const int sp = blockIdx.y;
    const int b = bh >> 3, h = bh & 7;
    const float* qp = q + ((size_t)b * CDIM + h * CH) * HW;
    const float* kp = k + ((size_t)b * CDIM + h * CH) * HW;

    __shared__ float qs[CH][36];
    __shared__ float ks[CH][36];

    const int tid = threadIdx.x;
    const int tx = tid % 16, ty = tid / 16;
    const int c0 = ty * 3, d0 = tx * 3;

    float acc[3][3] = {{0.f}};
    const int perSplit = HW / NSPLIT;
    const int base = sp * perSplit;

    for (int t0 = 0; t0 < perSplit; t0 += 32) {
        for (int i = tid; i < CH * 8; i += 256) {
            int cc = i >> 3, kq = i & 7;
            float4 vq = *(const float4*)(qp + (size_t)cc * HW + base + t0 + kq * 4);
            float4 vk = *(const float4*)(kp + (size_t)cc * HW + base + t0 + kq * 4);
            *(float4*)&qs[cc][kq * 4] = vq;
            *(float4*)&ks[cc][kq * 4] = vk;
        }
        __syncthreads();
#pragma unroll
        for (int kk = 0; kk < 32; kk++) {
            float a0 = qs[c0 + 0][kk], a1 = qs[c0 + 1][kk], a2 = qs[c0 + 2][kk];
            float e0 = ks[d0 + 0][kk], e1 = ks[d0 + 1][kk], e2 = ks[d0 + 2][kk];
            acc[0][0] += a0 * e0; acc[0][1] += a0 * e1; acc[0][2] += a0 * e2;
            acc[1][0] += a1 * e0; acc[1][1] += a1 * e1; acc[1][2] += a1 * e2;
            acc[2][0] += a2 * e0; acc[2][1] += a2 * e1; acc[2][2] += a2 * e2;
        }
        __syncthreads();
    }

    float* ap = g_attn + (size_t)bh * CH * CH;
#pragma unroll
    for (int i = 0; i < 3; i++)
#pragma unroll
        for (int j = 0; j < 3; j++)
            atomicAdd(&ap[(c0 + i) * CH + d0 + j], acc[i][j]);
}

// ---------------------------------------------------------------------------
// Softmax with norm scaling + temperature
// ---------------------------------------------------------------------------
__global__ void softmax_kernel(const float* __restrict__ invq, const float* __restrict__ nk,
                               const float* __restrict__ temp)
{
    const int r = blockIdx.x;
    const int bh = r / CH, c = r % CH;
    const int b = bh >> 3, h = bh & 7;
    const int lane = threadIdx.x;

    float* row = g_attn + (size_t)bh * CH * CH + (size_t)c * CH;
    const float iq = invq[b * CDIM + h * CH + c];
    const float tp = temp[h];

    const float ik0 = 1.f / fmaxf(sqrtf(nk[b * CDIM + h * CH + lane]), 1e-12f);
    float l0 = row[lane] * iq * ik0 * tp;
    float l1 = -INFINITY;
    if (lane < CH - 32) {
        const float ik1 = 1.f / fmaxf(sqrtf(nk[b * CDIM + h * CH + lane + 32]), 1e-12f);
        l1 = row[lane + 32] * iq * ik1 * tp;
    }

    float m = fmaxf(l0, l1);
#pragma unroll
    for (int off = 16; off > 0; off >>= 1)
        m = fmaxf(m, __shfl_xor_sync(0xffffffff, m, off));

    float e0 = expf(l0 - m);
    float e1 = (lane < CH - 32) ? expf(l1 - m) : 0.f;
    float s = e0 + e1;
#pragma unroll
    for (int off = 16; off > 0; off >>= 1)
        s += __shfl_xor_sync(0xffffffff, s, off);

    float rs = 1.f / s;
    row[lane] = e0 * rs;
    if (lane < CH - 32) row[lane + 32] = e1 * rs;
}

// ---------------------------------------------------------------------------
// out[bh][c][p] = sum_d attn[bh][c][d] * v[bh][d][p]
// ---------------------------------------------------------------------------
__global__ __launch_bounds__(128)
void attn_out_kernel(const float* __restrict__ v, float* __restrict__ out)
{
    const int bh = blockIdx.y;
    const int b = bh >> 3, h = bh & 7;
    const int p = blockIdx.x * blockDim.x + threadIdx.x;

    __shared__ float as[CH][CH];
    for (int i = threadIdx.x; i < CH * CH; i += blockDim.x)
        as[i / CH][i % CH] = g_attn[(size_t)bh * CH * CH + i];
    __syncthreads();

    const float* vp = v + ((size_t)b * CDIM + h * CH) * HW;
    float*       op = out + ((size_t)b * CDIM + h * CH) * HW;

    float vr[CH];
#pragma unroll
    for (int d = 0; d < CH; d++) vr[d] = vp[(size_t)d * HW + p];

#pragma unroll
    for (int c = 0; c < CH; c++) {
        float s = 0.f;
#pragma unroll
        for (int d = 0; d < CH; d++) s += as[c][d] * vr[d];
        op[(size_t)c * HW + p] = s;
    }
}

// ---------------------------------------------------------------------------
// Host launcher
// ---------------------------------------------------------------------------
extern "C" void kernel_launch(void* const* d_in, const int* in_sizes, int n_in,
                              void* d_out, int out_size)
{
    const float* x      = (const float*)d_in[0];
    const float* t      = (const float*)d_in[1];
    const float* w_q    = (const float*)d_in[2];
    const float* w_q_dw = (const float*)d_in[3];
    const float* w_qT   = (const float*)d_in[4];
    const float* w_qT_dw= (const float*)d_in[5];
    const float* w_qcat = (const float*)d_in[6];
    const float* w_k    = (const float*)d_in[7];
    const float* w_k_dw = (const float*)d_in[8];
    const float* w_v    = (const float*)d_in[9];
    const float* w_v_dw = (const float*)d_in[10];
    const float* temp   = (const float*)d_in[11];
    float* out = (float*)d_out;

    float *p_tmp, *p_cat, *p_k, *p_v, *p_q, *p_invq, *p_nk;
    cudaGetSymbolAddress((void**)&p_tmp, g_tmp);
    cudaGetSymbolAddress((void**)&p_cat, g_cat);
    cudaGetSymbolAddress((void**)&p_k,   g_k);
    cudaGetSymbolAddress((void**)&p_v,   g_v);
    cudaGetSymbolAddress((void**)&p_q,   g_q);
    cudaGetSymbolAddress((void**)&p_invq, g_invq);
    cudaGetSymbolAddress((void**)&p_nk,  g_nk);

    const int gemmSmem = SMEM_FLOATS * 4;             // ~74 KB dynamic smem
    static int smemSet = 0;
    if (!smemSet) {
        cudaFuncSetAttribute(tgemm_kernel,
                             cudaFuncAttributeMaxDynamicSharedMemorySize, gemmSmem);
        smemSet = 1;
    }

    const dim3 gemmGrid(CDIM / BM, HW / BN, BATCH);   // 3 x 128 x 4
    const dim3 dwGrid(HH / DTY, CDIM, BATCH);         // 8 x 384 x 4
    const size_t bsIn  = (size_t)CDIM * HW;
    const size_t bsCat = (size_t)2 * CDIM * HW;

    zero_kernel<<<(BATCH * HEADS * CH * CH + 255) / 256, 256>>>();

    // q branch
    tgemm_kernel<<<gemmGrid, 256, gemmSmem>>>(w_q, x, p_tmp, CDIM, HW, CDIM);
    dw3x3_kernel<<<dwGrid, 256>>>(p_tmp, w_q_dw, p_cat, bsIn, bsCat, 0, nullptr);

    // qT branch
    tgemm_kernel<<<gemmGrid, 256, gemmSmem>>>(w_qT, t, p_tmp, CDIM, HW, CDIM);
    dw3x3_kernel<<<dwGrid, 256>>>(p_tmp, w_qT_dw, p_cat, bsIn, bsCat, CDIM, nullptr);

    // k branch (fused sum-of-squares)
    tgemm_kernel<<<gemmGrid, 256, gemmSmem>>>(w_k, x, p_tmp, CDIM, HW, CDIM);
    dw3x3_kernel<<<dwGrid, 256>>>(p_tmp, w_k_dw, p_k, bsIn, bsIn, 0, p_nk);

    // v branch
    tgemm_kernel<<<gemmGrid, 256, gemmSmem>>>(w_v, x, p_tmp, CDIM, HW, CDIM);
    dw3x3_kernel<<<dwGrid, 256>>>(p_tmp, w_v_dw, p_v, bsIn, bsIn, 0, nullptr);

    // q = pw(concat, w_qcat): K = 768
    tgemm_kernel<<<gemmGrid, 256, gemmSmem>>>(w_qcat, p_cat, p_q, CDIM, HW, 2 * CDIM);

    rownorm_kernel<<<BATCH * CDIM, 256>>>(p_q, p_invq);

    attn_score_kernel<<<dim3(BATCH * HEADS, NSPLIT), 256>>>(p_q, p_k);
    softmax_kernel<<<BATCH * HEADS * CH, 32>>>(p_invq, p_nk, temp);

    attn_out_kernel<<<dim3(HW / 128, BATCH * HEADS), 128>>>(p_v, out);
}

// round 5
// speedup vs baseline: 1.7008x; 1.0759x over previous
#include <cuda_runtime.h>
#include <cuda_bf16.h>
#include <math.h>
#include <stdint.h>

// Problem constants
#define BATCH 4
#define CDIM  384
#define HEADS 8
#define CH    48
#define HH    128
#define WW    128
#define HW    16384

// ---------------------------------------------------------------------------
// Scratch buffers
// ---------------------------------------------------------------------------
__device__ float g_tmp[(size_t)BATCH * CDIM * HW];
__device__ float g_cat[(size_t)BATCH * 2 * CDIM * HW];
__device__ float g_k  [(size_t)BATCH * CDIM * HW];
__device__ float g_v  [(size_t)BATCH * CDIM * HW];
__device__ float g_q  [(size_t)BATCH * CDIM * HW];
__device__ float g_attn[(size_t)BATCH * HEADS * CH * CH];
__device__ float g_invq[BATCH * CDIM];
__device__ float g_nk[BATCH * CDIM];
// tf32-converted weights: wq, wqT, wk, wv (384*384 each) + wqcat (384*768)
#define WSZ (CDIM * CDIM)
__device__ uint32_t g_wtf[4 * WSZ + CDIM * 2 * CDIM];

// ---------------------------------------------------------------------------
// TF32 tensor-core GEMM, 4-stage cp.async pipeline, ldmatrix A fragments.
// A holds pre-converted tf32 bits. C[b] = A (MxK) @ B[b] (KxN).
// ---------------------------------------------------------------------------
#define BM 128
#define BN 128
#define BK 16
#define STAGES 4
#define ASTRIDE 20
#define BSTRIDE 136
#define A_STAGE (BM * ASTRIDE)
#define B_STAGE (BK * BSTRIDE)
#define SMEM_FLOATS (STAGES * (A_STAGE + B_STAGE))

__device__ __forceinline__ uint32_t f2tf32(float x) {
    uint32_t r;
    asm("cvt.rna.tf32.f32 %0, %1;" : "=r"(r) : "f"(x));
    return r;
}

__device__ __forceinline__ void mma_tf32(float* c, const uint32_t* a, const uint32_t* b) {
    asm volatile(
        "mma.sync.aligned.m16n8k8.row.col.f32.tf32.tf32.f32 "
        "{%0,%1,%2,%3}, {%4,%5,%6,%7}, {%8,%9}, {%0,%1,%2,%3};\n"
        : "+f"(c[0]), "+f"(c[1]), "+f"(c[2]), "+f"(c[3])
        : "r"(a[0]), "r"(a[1]), "r"(a[2]), "r"(a[3]), "r"(b[0]), "r"(b[1]));
}

__device__ __forceinline__ void cp16(uint32_t smem_addr, const void* gptr) {
    asm volatile("cp.async.cg.shared.global [%0], [%1], 16;\n"
                 :: "r"(smem_addr), "l"(gptr));
}

__device__ __forceinline__ void ldsm4(uint32_t* r, uint32_t addr) {
    asm volatile("ldmatrix.sync.aligned.m8n8.x4.b16 {%0,%1,%2,%3}, [%4];\n"
                 : "=r"(r[0]), "=r"(r[1]), "=r"(r[2]), "=r"(r[3]) : "r"(addr));
}

__global__ __launch_bounds__(256, 2)
void tgemm_kernel(const uint32_t* __restrict__ A, const float* __restrict__ Bb,
                  float* __restrict__ Cb, int M, int N, int K)
{
    const int bz = blockIdx.z;
    const float* B = Bb + (size_t)bz * K * N;
    float*       C = Cb + (size_t)bz * M * N;

    extern __shared__ float smem[];
    float* Asm = smem;                       // [STAGES][BM][ASTRIDE] (tf32 bits)
    float* Bsm = smem + STAGES * A_STAGE;    // [STAGES][BK][BSTRIDE] (fp32)

    const int tid  = threadIdx.x;
    const int lane = tid & 31, warp = tid >> 5;
    const int g = lane >> 2, tig = lane & 3;
    const int wm = (warp >> 2) * 64;
    const int wn = (warp & 3) * 32;
    const int brow = blockIdx.x * BM;
    const int bcol = blockIdx.y * BN;

    // cp.async mapping
    const int am  = tid & 127;
    const int aq0 = (tid >> 7) * 2;
    const int bkk = tid >> 4;
    const int bq0 = (tid & 15) * 2;

    const uint32_t* Abase = A + (size_t)(brow + am) * K;
    const float*    Bbase = B + bcol;

    const uint32_t sA = (uint32_t)__cvta_generic_to_shared(Asm);
    const uint32_t sB = (uint32_t)__cvta_generic_to_shared(Bsm);

    // ldmatrix per-thread tile coordinates
    const int ltile = lane >> 3;                    // 0..3
    const int lrow  = (ltile & 1) * 8 + (lane & 7); // row within 16-row block
    const int lcol  = (ltile >> 1) * 4;             // 0 or 4

    const int iters = K / BK;

#define ISSUE(stage_, J_)                                                     \
    do {                                                                      \
        const int s_ = (stage_);                                              \
        const uint32_t* Ap_ = Abase + (J_)*BK;                                \
        const float*    Bp_ = Bbase + (size_t)((J_)*BK) * N;                  \
        cp16(sA + (s_ * A_STAGE + am * ASTRIDE + aq0 * 4) * 4, Ap_ + aq0 * 4);\
        cp16(sA + (s_ * A_STAGE + am * ASTRIDE + (aq0 + 1) * 4) * 4,          \
             Ap_ + (aq0 + 1) * 4);                                            \
        cp16(sB + (s_ * B_STAGE + bkk * BSTRIDE + bq0 * 4) * 4,               \
             Bp_ + (size_t)bkk * N + bq0 * 4);                                \
        cp16(sB + (s_ * B_STAGE + bkk * BSTRIDE + (bq0 + 1) * 4) * 4,         \
             Bp_ + (size_t)bkk * N + (bq0 + 1) * 4);                          \
    } while (0)

#pragma unroll
    for (int s = 0; s < STAGES - 1; s++) {
        ISSUE(s, s);
        asm volatile("cp.async.commit_group;\n" ::: "memory");
    }

    float acc[4][4][4];
#pragma unroll
    for (int i = 0; i < 4; i++)
#pragma unroll
        for (int j = 0; j < 4; j++)
#pragma unroll
            for (int r = 0; r < 4; r++) acc[i][j][r] = 0.f;

    int buf = 0;
    for (int it = 0; it < iters; ++it) {
        asm volatile("cp.async.wait_group %0;\n" :: "n"(STAGES - 2) : "memory");
        __syncthreads();

        const uint32_t aStage = sA + buf * A_STAGE * 4;
        const float* Bs = Bsm + buf * B_STAGE;

#pragma unroll
        for (int kk = 0; kk < BK; kk += 8) {
            uint32_t af[4][4], bf[4][2];
#pragma unroll
            for (int i = 0; i < 4; i++) {
                const uint32_t addr =
                    aStage + ((wm + i * 16 + lrow) * ASTRIDE + kk + lcol) * 4;
                ldsm4(af[i], addr);
            }
#pragma unroll
            for (int j = 0; j < 4; j++) {
                const int nr = wn + j * 8 + g;
                bf[j][0] = f2tf32(Bs[(kk + tig) * BSTRIDE + nr]);
                bf[j][1] = f2tf32(Bs[(kk + tig + 4) * BSTRIDE + nr]);
            }
#pragma unroll
            for (int i = 0; i < 4; i++)
#pragma unroll
                for (int j = 0; j < 4; j++)
                    mma_tf32(acc[i][j], af[i], bf[j]);
        }

        const int nj = it + STAGES - 1;
        if (nj < iters) {
            ISSUE(nj & (STAGES - 1), nj);
        }
        asm volatile("cp.async.commit_group;\n" ::: "memory");
        buf = (buf + 1) & (STAGES - 1);
    }
#undef ISSUE

#pragma unroll
    for (int i = 0; i < 4; i++) {
        const int r0 = brow + wm + i * 16 + g;
#pragma unroll
        for (int j = 0; j < 4; j++) {
            const int cc = bcol + wn + j * 8 + 2 * tig;
            *(float2*)&C[(size_t)r0 * N + cc]       = make_float2(acc[i][j][0], acc[i][j][1]);
            *(float2*)&C[(size_t)(r0 + 8) * N + cc] = make_float2(acc[i][j][2], acc[i][j][3]);
        }
    }
}

// ---------------------------------------------------------------------------
// Weight pre-conversion to tf32 bits
// ---------------------------------------------------------------------------
__global__ void cvtw_kernel(const float* __restrict__ src, uint32_t* __restrict__ dst, int n)
{
    int i = blockIdx.x * blockDim.x + threadIdx.x;
    if (i < n) dst[i] = f2tf32(src[i]);
}

// ---------------------------------------------------------------------------
// Depthwise 3x3 SAME conv, vectorized, optional fused sum-of-squares
// ---------------------------------------------------------------------------
#define DTY 16
__global__ __launch_bounds__(256)
void dw3x3_kernel(const float* __restrict__ in, const float* __restrict__ w,
                  float* __restrict__ out,
                  size_t inBatchStride, size_t outBatchStride, int outChanOff,
                  float* __restrict__ nrm)
{
    const int c = blockIdx.y;
    const int b = blockIdx.z;
    const int y0 = blockIdx.x * DTY;
    const float* ip = in + (size_t)b * inBatchStride + (size_t)c * HW;
    float*       op = out + (size_t)b * outBatchStride + (size_t)(c + outChanOff) * HW;
    const float* wc = w + c * 9;

    __shared__ float sm[DTY + 2][136];

    const int tid = threadIdx.x;
    const float4 z4 = make_float4(0.f, 0.f, 0.f, 0.f);
    for (int s = tid; s < (DTY + 2) * 34; s += 256) {
        const int r = s / 34;
        const int q = s - r * 34;
        const int gy = y0 - 1 + r;
        if (q < 32) {
            float4 v = (gy >= 0 && gy < HH) ? *(const float4*)(ip + gy * WW + q * 4) : z4;
            *(float4*)&sm[r][4 + q * 4] = v;
        } else if (q == 32) {
            sm[r][3] = 0.f;
        } else {
            sm[r][4 + WW] = 0.f;
        }
    }
    __syncthreads();

    const float w00 = wc[0], w01 = wc[1], w02 = wc[2];
    const float w10 = wc[3], w11 = wc[4], w12 = wc[5];
    const float w20 = wc[6], w21 = wc[7], w22 = wc[8];

    float s2 = 0.f;
#pragma unroll
    for (int i = 0; i < (DTY * 32) / 256; i++) {
        const int oid = tid + i * 256;
        const int y = oid >> 5;
        const int xq = oid & 31;
        float o0 = 0.f, o1 = 0.f, o2 = 0.f, o3 = 0.f;
#pragma unroll
        for (int r = 0; r < 3; r++) {
            const float wr0 = (r == 0) ? w00 : (r == 1) ? w10 : w20;
            const float wr1 = (r == 0) ? w01 : (r == 1) ? w11 : w21;
            const float wr2 = (r == 0) ? w02 : (r == 1) ? w12 : w22;
            const float4 cc = *(const float4*)&sm[y + r][4 + xq * 4];
            const float l  = sm[y + r][3 + xq * 4];
            const float rr = sm[y + r][8 + xq * 4];
            o0 += l    * wr0 + cc.x * wr1 + cc.y * wr2;
            o1 += cc.x * wr0 + cc.y * wr1 + cc.z * wr2;
            o2 += cc.y * wr0 + cc.z * wr1 + cc.w * wr2;
            o3 += cc.z * wr0 + cc.w * wr1 + rr   * wr2;
        }
        *(float4*)(op + (y0 + y) * WW + xq * 4) = make_float4(o0, o1, o2, o3);
        s2 += o0 * o0 + o1 * o1 + o2 * o2 + o3 * o3;
    }

    if (nrm) {
#pragma unroll
        for (int off = 16; off > 0; off >>= 1)
            s2 += __shfl_xor_sync(0xffffffff, s2, off);
        __shared__ float wred[8];
        if ((tid & 31) == 0) wred[tid >> 5] = s2;
        __syncthreads();
        if (tid == 0) {
            float tot = 0.f;
#pragma unroll
            for (int ww2 = 0; ww2 < 8; ww2++) tot += wred[ww2];
            atomicAdd(&nrm[b * CDIM + c], tot);
        }
    }
}

// ---------------------------------------------------------------------------
// Row L2 inverse norm over HW
// ---------------------------------------------------------------------------
__global__ void rownorm_kernel(const float* __restrict__ in, float* __restrict__ inv)
{
    const int r = blockIdx.x;
    const float* p = in + (size_t)r * HW;
    float s = 0.f;
    for (int i = threadIdx.x; i < HW / 4; i += blockDim.x) {
        float4 v = ((const float4*)p)[i];
        s += v.x * v.x + v.y * v.y + v.z * v.z + v.w * v.w;
    }
    __shared__ float red[256];
    red[threadIdx.x] = s;
    __syncthreads();
    for (int off = 128; off > 0; off >>= 1) {
        if (threadIdx.x < off) red[threadIdx.x] += red[threadIdx.x + off];
        __syncthreads();
    }
    if (threadIdx.x == 0)
        inv[r] = 1.f / fmaxf(sqrtf(red[0]), 1e-12f);
}

__global__ void zero_kernel()
{
    int i = blockIdx.x * blockDim.x + threadIdx.x;
    if (i < BATCH * HEADS * CH * CH) g_attn[i] = 0.f;
    if (i < BATCH * CDIM) g_nk[i] = 0.f;
}

// ---------------------------------------------------------------------------
// attn_raw[bh][c][d] += sum_n q[c][n]*k[d][n]
// ---------------------------------------------------------------------------
#define NSPLIT 16
__global__ void attn_score_kernel(const float* __restrict__ q, const float* __restrict__ k)
{
    const int bh = blockIdx.x;
    const int sp = blockIdx.y;
    const int b = bh >> 3, h = bh & 7;
    const float* qp = q + ((size_t)b * CDIM + h * CH) * HW;
    const float* kp = k + ((size_t)b * CDIM + h * CH) * HW;

    __shared__ float qs[CH][36];
    __shared__ float ks[CH][36];

    const int tid = threadIdx.x;
    const int tx = tid % 16, ty = tid / 16;
    const int c0 = ty * 3, d0 = tx * 3;

    float acc[3][3] = {{0.f}};
    const int perSplit = HW / NSPLIT;
    const int base = sp * perSplit;

    for (int t0 = 0; t0 < perSplit; t0 += 32) {
        for (int i = tid; i < CH * 8; i += 256) {
            int cc = i >> 3, kq = i & 7;
            float4 vq = *(const float4*)(qp + (size_t)cc * HW + base + t0 + kq * 4);
            float4 vk = *(const float4*)(kp + (size_t)cc * HW + base + t0 + kq * 4);
            *(float4*)&qs[cc][kq * 4] = vq;
            *(float4*)&ks[cc][kq * 4] = vk;
        }
        __syncthreads();
#pragma unroll
        for (int kk = 0; kk < 32; kk++) {
            float a0 = qs[c0 + 0][kk], a1 = qs[c0 + 1][kk], a2 = qs[c0 + 2][kk];
            float e0 = ks[d0 + 0][kk], e1 = ks[d0 + 1][kk], e2 = ks[d0 + 2][kk];
            acc[0][0] += a0 * e0; acc[0][1] += a0 * e1; acc[0][2] += a0 * e2;
            acc[1][0] += a1 * e0; acc[1][1] += a1 * e1; acc[1][2] += a1 * e2;
            acc[2][0] += a2 * e0; acc[2][1] += a2 * e1; acc[2][2] += a2 * e2;
        }
        __syncthreads();
    }

    float* ap = g_attn + (size_t)bh * CH * CH;
#pragma unroll
    for (int i = 0; i < 3; i++)
#pragma unroll
        for (int j = 0; j < 3; j++)
            atomicAdd(&ap[(c0 + i) * CH + d0 + j], acc[i][j]);
}

// ---------------------------------------------------------------------------
// Softmax with norm scaling + temperature
// ---------------------------------------------------------------------------
__global__ void softmax_kernel(const float* __restrict__ invq, const float* __restrict__ nk,
                               const float* __restrict__ temp)
{
    const int r = blockIdx.x;
    const int bh = r / CH, c = r % CH;
    const int b = bh >> 3, h = bh & 7;
    const int lane = threadIdx.x;

    float* row = g_attn + (size_t)bh * CH * CH + (size_t)c * CH;
    const float iq = invq[b * CDIM + h * CH + c];
    const float tp = temp[h];

    const float ik0 = 1.f / fmaxf(sqrtf(nk[b * CDIM + h * CH + lane]), 1e-12f);
    float l0 = row[lane] * iq * ik0 * tp;
    float l1 = -INFINITY;
    if (lane < CH - 32) {
        const float ik1 = 1.f / fmaxf(sqrtf(nk[b * CDIM + h * CH + lane + 32]), 1e-12f);
        l1 = row[lane + 32] * iq * ik1 * tp;
    }

    float m = fmaxf(l0, l1);
#pragma unroll
    for (int off = 16; off > 0; off >>= 1)
        m = fmaxf(m, __shfl_xor_sync(0xffffffff, m, off));

    float e0 = expf(l0 - m);
    float e1 = (lane < CH - 32) ? expf(l1 - m) : 0.f;
    float s = e0 + e1;
#pragma unroll
    for (int off = 16; off > 0; off >>= 1)
        s += __shfl_xor_sync(0xffffffff, s, off);

    float rs = 1.f / s;
    row[lane] = e0 * rs;
    if (lane < CH - 32) row[lane + 32] = e1 * rs;
}

// ---------------------------------------------------------------------------
// out[bh][c][p] = sum_d attn[bh][c][d] * v[bh][d][p]
// ---------------------------------------------------------------------------
__global__ __launch_bounds__(128)
void attn_out_kernel(const float* __restrict__ v, float* __restrict__ out)
{
    const int bh = blockIdx.y;
    const int b = bh >> 3, h = bh & 7;
    const int p = blockIdx.x * blockDim.x + threadIdx.x;

    __shared__ float as[CH][CH];
    for (int i = threadIdx.x; i < CH * CH; i += blockDim.x)
        as[i / CH][i % CH] = g_attn[(size_t)bh * CH * CH + i];
    __syncthreads();

    const float* vp = v + ((size_t)b * CDIM + h * CH) * HW;
    float*       op = out + ((size_t)b * CDIM + h * CH) * HW;

    float vr[CH];
#pragma unroll
    for (int d = 0; d < CH; d++) vr[d] = vp[(size_t)d * HW + p];

#pragma unroll
    for (int c = 0; c < CH; c++) {
        float s = 0.f;
#pragma unroll
        for (int d = 0; d < CH; d++) s += as[c][d] * vr[d];
        op[(size_t)c * HW + p] = s;
    }
}

// ---------------------------------------------------------------------------
// Host launcher
// ---------------------------------------------------------------------------
extern "C" void kernel_launch(void* const* d_in, const int* in_sizes, int n_in,
                              void* d_out, int out_size)
{
    const float* x      = (const float*)d_in[0];
    const float* t      = (const float*)d_in[1];
    const float* w_q    = (const float*)d_in[2];
    const float* w_q_dw = (const float*)d_in[3];
    const float* w_qT   = (const float*)d_in[4];
    const float* w_qT_dw= (const float*)d_in[5];
    const float* w_qcat = (const float*)d_in[6];
    const float* w_k    = (const float*)d_in[7];
    const float* w_k_dw = (const float*)d_in[8];
    const float* w_v    = (const float*)d_in[9];
    const float* w_v_dw = (const float*)d_in[10];
    const float* temp   = (const float*)d_in[11];
    float* out = (float*)d_out;

    float *p_tmp, *p_cat, *p_k, *p_v, *p_q, *p_invq, *p_nk;
    uint32_t* p_wtf;
    cudaGetSymbolAddress((void**)&p_tmp, g_tmp);
    cudaGetSymbolAddress((void**)&p_cat, g_cat);
    cudaGetSymbolAddress((void**)&p_k,   g_k);
    cudaGetSymbolAddress((void**)&p_v,   g_v);
    cudaGetSymbolAddress((void**)&p_q,   g_q);
    cudaGetSymbolAddress((void**)&p_invq, g_invq);
    cudaGetSymbolAddress((void**)&p_nk,  g_nk);
    cudaGetSymbolAddress((void**)&p_wtf, g_wtf);

    uint32_t* wq_t    = p_wtf;
    uint32_t* wqT_t   = p_wtf + WSZ;
    uint32_t* wk_t    = p_wtf + 2 * WSZ;
    uint32_t* wv_t    = p_wtf + 3 * WSZ;
    uint32_t* wqcat_t = p_wtf + 4 * WSZ;

    const int gemmSmem = SMEM_FLOATS * 4;
    static int smemSet = 0;
    if (!smemSet) {
        cudaFuncSetAttribute(tgemm_kernel,
                             cudaFuncAttributeMaxDynamicSharedMemorySize, gemmSmem);
        smemSet = 1;
    }

    const dim3 gemmGrid(CDIM / BM, HW / BN, BATCH);   // 3 x 128 x 4
    const dim3 dwGrid(HH / DTY, CDIM, BATCH);
    const size_t bsIn  = (size_t)CDIM * HW;
    const size_t bsCat = (size_t)2 * CDIM * HW;

    // weight conversion + zeroing (cheap)
    cvtw_kernel<<<(WSZ + 255) / 256, 256>>>(w_q,    wq_t,    WSZ);
    cvtw_kernel<<<(WSZ + 255) / 256, 256>>>(w_qT,   wqT_t,   WSZ);
    cvtw_kernel<<<(WSZ + 255) / 256, 256>>>(w_k,    wk_t,    WSZ);
    cvtw_kernel<<<(WSZ + 255) / 256, 256>>>(w_v,    wv_t,    WSZ);
    cvtw_kernel<<<(2 * WSZ + 255) / 256, 256>>>(w_qcat, wqcat_t, 2 * WSZ);
    zero_kernel<<<(BATCH * HEADS * CH * CH + 255) / 256, 256>>>();

    // q branch
    tgemm_kernel<<<gemmGrid, 256, gemmSmem>>>(wq_t, x, p_tmp, CDIM, HW, CDIM);
    dw3x3_kernel<<<dwGrid, 256>>>(p_tmp, w_q_dw, p_cat, bsIn, bsCat, 0, nullptr);

    // qT branch
    tgemm_kernel<<<gemmGrid, 256, gemmSmem>>>(wqT_t, t, p_tmp, CDIM, HW, CDIM);
    dw3x3_kernel<<<dwGrid, 256>>>(p_tmp, w_qT_dw, p_cat, bsIn, bsCat, CDIM, nullptr);

    // k branch (fused sum-of-squares)
    tgemm_kernel<<<gemmGrid, 256, gemmSmem>>>(wk_t, x, p_tmp, CDIM, HW, CDIM);
    dw3x3_kernel<<<dwGrid, 256>>>(p_tmp, w_k_dw, p_k, bsIn, bsIn, 0, p_nk);

    // v branch
    tgemm_kernel<<<gemmGrid, 256, gemmSmem>>>(wv_t, x, p_tmp, CDIM, HW, CDIM);
    dw3x3_kernel<<<dwGrid, 256>>>(p_tmp, w_v_dw, p_v, bsIn, bsIn, 0, nullptr);

    // q = pw(concat): K = 768
    tgemm_kernel<<<gemmGrid, 256, gemmSmem>>>(wqcat_t, p_cat, p_q, CDIM, HW, 2 * CDIM);

    rownorm_kernel<<<BATCH * CDIM, 256>>>(p_q, p_invq);

    attn_score_kernel<<<dim3(BATCH * HEADS, NSPLIT), 256>>>(p_q, p_k);
    softmax_kernel<<<BATCH * HEADS * CH, 32>>>(p_invq, p_nk, temp);

    attn_out_kernel<<<dim3(HW / 128, BATCH * HEADS), 128>>>(p_v, out);
}

// round 7
// speedup vs baseline: 1.7578x; 1.0335x over previous
#include <cuda_runtime.h>
#include <cuda_bf16.h>
#include <math.h>
#include <stdint.h>

// Problem constants
#define BATCH 4
#define CDIM  384
#define HEADS 8
#define CH    48
#define HH    128
#define WW    128
#define HW    16384

// ---------------------------------------------------------------------------
// Scratch buffers
// ---------------------------------------------------------------------------
__device__ float    g_qkv[(size_t)BATCH * 3 * CDIM * HW];   // fused q/k/v pw out
__device__ float    g_tmp[(size_t)BATCH * CDIM * HW];       // qT pw out
__device__ uint32_t g_cat[(size_t)BATCH * 2 * CDIM * HW];   // dw(q);dw(qT) as tf32 bits
__device__ float    g_k  [(size_t)BATCH * CDIM * HW];
__device__ float    g_v  [(size_t)BATCH * CDIM * HW];
__device__ float    g_q  [(size_t)BATCH * CDIM * HW];
__device__ float    g_attn[(size_t)BATCH * HEADS * CH * CH];
__device__ float    g_nq[BATCH * CDIM];                     // q sum-of-squares
__device__ float    g_nk[BATCH * CDIM];                     // k sum-of-squares
#define WSZ (CDIM * CDIM)
__device__ uint32_t g_wtf[6 * WSZ];                         // [wq;wk;wv] wqT wqcat
__device__ uint32_t g_xtf[(size_t)BATCH * CDIM * HW];       // x as tf32 bits
__device__ uint32_t g_ttf[(size_t)BATCH * CDIM * HW];       // t as tf32 bits

// ---------------------------------------------------------------------------
// TF32 tensor-core GEMM, 4-stage cp.async, ldmatrix A fragments.
// A and B both hold pre-converted tf32 bits. C[b] = A (MxK) @ B[b] (KxN).
// Optional fused per-row sum-of-squares accumulation (nrm != nullptr).
// ---------------------------------------------------------------------------
#define BM 128
#define BN 128
#define BK 16
#define STAGES 4
#define ASTRIDE 20
#define BSTRIDE 136
#define A_STAGE (BM * ASTRIDE)
#define B_STAGE (BK * BSTRIDE)
#define SMEM_FLOATS (STAGES * (A_STAGE + B_STAGE))

__device__ __forceinline__ uint32_t f2tf32(float x) {
    uint32_t r;
    asm("cvt.rna.tf32.f32 %0, %1;" : "=r"(r) : "f"(x));
    return r;
}

__device__ __forceinline__ void mma_tf32(float* c, const uint32_t* a, const uint32_t* b) {
    asm volatile(
        "mma.sync.aligned.m16n8k8.row.col.f32.tf32.tf32.f32 "
        "{%0,%1,%2,%3}, {%4,%5,%6,%7}, {%8,%9}, {%0,%1,%2,%3};\n"
        : "+f"(c[0]), "+f"(c[1]), "+f"(c[2]), "+f"(c[3])
        : "r"(a[0]), "r"(a[1]), "r"(a[2]), "r"(a[3]), "r"(b[0]), "r"(b[1]));
}

__device__ __forceinline__ void cp16(uint32_t smem_addr, const void* gptr) {
    asm volatile("cp.async.cg.shared.global [%0], [%1], 16;\n"
                 :: "r"(smem_addr), "l"(gptr));
}

__device__ __forceinline__ void ldsm4(uint32_t* r, uint32_t addr) {
    asm volatile("ldmatrix.sync.aligned.m8n8.x4.b16 {%0,%1,%2,%3}, [%4];\n"
                 : "=r"(r[0]), "=r"(r[1]), "=r"(r[2]), "=r"(r[3]) : "r"(addr));
}

__global__ __launch_bounds__(256, 2)
void tgemm_kernel(const uint32_t* __restrict__ A, const uint32_t* __restrict__ Bb,
                  float* __restrict__ Cb, int M, int N, int K,
                  float* __restrict__ nrm)
{
    const int bz = blockIdx.z;
    const uint32_t* B = Bb + (size_t)bz * K * N;
    float*          C = Cb + (size_t)bz * M * N;

    extern __shared__ float smem[];
    uint32_t* Asm = (uint32_t*)smem;                        // [STAGES][BM][ASTRIDE]
    uint32_t* Bsm = (uint32_t*)smem + STAGES * A_STAGE;     // [STAGES][BK][BSTRIDE]

    const int tid  = threadIdx.x;
    const int lane = tid & 31, warp = tid >> 5;
    const int g = lane >> 2, tig = lane & 3;
    const int wm = (warp >> 2) * 64;
    const int wn = (warp & 3) * 32;
    const int brow = blockIdx.x * BM;
    const int bcol = blockIdx.y * BN;

    const int am  = tid & 127;
    const int aq0 = (tid >> 7) * 2;
    const int bkk = tid >> 4;
    const int bq0 = (tid & 15) * 2;

    const uint32_t* Abase = A + (size_t)(brow + am) * K;
    const uint32_t* Bbase = B + bcol;

    const uint32_t sA = (uint32_t)__cvta_generic_to_shared(Asm);
    const uint32_t sB = (uint32_t)__cvta_generic_to_shared(Bsm);

    const int ltile = lane >> 3;
    const int lrow  = (ltile & 1) * 8 + (lane & 7);
    const int lcol  = (ltile >> 1) * 4;

    const int iters = K / BK;

#define ISSUE(stage_, J_)                                                     \
    do {                                                                      \
        const int s_ = (stage_);                                              \
        const uint32_t* Ap_ = Abase + (J_)*BK;                                \
        const uint32_t* Bp_ = Bbase + (size_t)((J_)*BK) * N;                  \
        cp16(sA + (s_ * A_STAGE + am * ASTRIDE + aq0 * 4) * 4, Ap_ + aq0 * 4);\
        cp16(sA + (s_ * A_STAGE + am * ASTRIDE + (aq0 + 1) * 4) * 4,          \
             Ap_ + (aq0 + 1) * 4);                                            \
        cp16(sB + (s_ * B_STAGE + bkk * BSTRIDE + bq0 * 4) * 4,               \
             Bp_ + (size_t)bkk * N + bq0 * 4);                                \
        cp16(sB + (s_ * B_STAGE + bkk * BSTRIDE + (bq0 + 1) * 4) * 4,         \
             Bp_ + (size_t)bkk * N + (bq0 + 1) * 4);                          \
    } while (0)

#pragma unroll
    for (int s = 0; s < STAGES - 1; s++) {
        ISSUE(s, s);
        asm volatile("cp.async.commit_group;\n" ::: "memory");
    }

    float acc[4][4][4];
#pragma unroll
    for (int i = 0; i < 4; i++)
#pragma unroll
        for (int j = 0; j < 4; j++)
#pragma unroll
            for (int r = 0; r < 4; r++) acc[i][j][r] = 0.f;

    int buf = 0;
    for (int it = 0; it < iters; ++it) {
        asm volatile("cp.async.wait_group %0;\n" :: "n"(STAGES - 2) : "memory");
        __syncthreads();

        const uint32_t aStage = sA + buf * A_STAGE * 4;
        const uint32_t* Bs = Bsm + buf * B_STAGE;

#pragma unroll
        for (int kk = 0; kk < BK; kk += 8) {
            uint32_t af[4][4], bf[4][2];
#pragma unroll
            for (int i = 0; i < 4; i++) {
                const uint32_t addr =
                    aStage + ((wm + i * 16 + lrow) * ASTRIDE + kk + lcol) * 4;
                ldsm4(af[i], addr);
            }
#pragma unroll
            for (int j = 0; j < 4; j++) {
                const int nr = wn + j * 8 + g;
                bf[j][0] = Bs[(kk + tig) * BSTRIDE + nr];
                bf[j][1] = Bs[(kk + tig + 4) * BSTRIDE + nr];
            }
#pragma unroll
            for (int i = 0; i < 4; i++)
#pragma unroll
                for (int j = 0; j < 4; j++)
                    mma_tf32(acc[i][j], af[i], bf[j]);
        }

        const int nj = it + STAGES - 1;
        if (nj < iters) {
            ISSUE(nj & (STAGES - 1), nj);
        }
        asm volatile("cp.async.commit_group;\n" ::: "memory");
        buf = (buf + 1) & (STAGES - 1);
    }
#undef ISSUE

#pragma unroll
    for (int i = 0; i < 4; i++) {
        const int r0 = brow + wm + i * 16 + g;
#pragma unroll
        for (int j = 0; j < 4; j++) {
            const int cc = bcol + wn + j * 8 + 2 * tig;
            *(float2*)&C[(size_t)r0 * N + cc]       = make_float2(acc[i][j][0], acc[i][j][1]);
            *(float2*)&C[(size_t)(r0 + 8) * N + cc] = make_float2(acc[i][j][2], acc[i][j][3]);
        }
    }

    if (nrm) {
        float* nb = nrm + (size_t)bz * M;
#pragma unroll
        for (int i = 0; i < 4; i++) {
            float s0 = 0.f, s1 = 0.f;
#pragma unroll
            for (int j = 0; j < 4; j++) {
                s0 += acc[i][j][0] * acc[i][j][0] + acc[i][j][1] * acc[i][j][1];
                s1 += acc[i][j][2] * acc[i][j][2] + acc[i][j][3] * acc[i][j][3];
            }
            s0 += __shfl_xor_sync(0xffffffff, s0, 1);
            s0 += __shfl_xor_sync(0xffffffff, s0, 2);
            s1 += __shfl_xor_sync(0xffffffff, s1, 1);
            s1 += __shfl_xor_sync(0xffffffff, s1, 2);
            if (tig == 0) {
                const int r0 = brow + wm + i * 16 + g;
                atomicAdd(&nb[r0], s0);
                atomicAdd(&nb[r0 + 8], s1);
            }
        }
    }
}

// ---------------------------------------------------------------------------
// Weight / activation pre-conversion to tf32 bits
// ---------------------------------------------------------------------------
__global__ void cvtw_kernel(const float* __restrict__ src, uint32_t* __restrict__ dst, int n)
{
    int i = blockIdx.x * blockDim.x + threadIdx.x;
    if (i < n) dst[i] = f2tf32(src[i]);
}

__global__ void cvtx_kernel(const float4* __restrict__ src, uint4* __restrict__ dst, int n4)
{
    int i = blockIdx.x * blockDim.x + threadIdx.x;
    if (i < n4) {
        float4 v = src[i];
        dst[i] = make_uint4(f2tf32(v.x), f2tf32(v.y), f2tf32(v.z), f2tf32(v.w));
    }
}

// ---------------------------------------------------------------------------
// Depthwise 3x3 SAME conv; optional tf32-bit output, optional fused sumsq
// ---------------------------------------------------------------------------
#define DTY 16
__global__ __launch_bounds__(256)
void dw3x3_kernel(const float* __restrict__ in, const float* __restrict__ w,
                  void* __restrict__ out,
                  size_t inBatchStride, int inChanOff,
                  size_t outBatchStride, int outChanOff,
                  float* __restrict__ nrm, int cvtOut)
{
    const int c = blockIdx.y;
    const int b = blockIdx.z;
    const int y0 = blockIdx.x * DTY;
    const float* ip = in + (size_t)b * inBatchStride + (size_t)(c + inChanOff) * HW;
    const size_t oofs = (size_t)b * outBatchStride + (size_t)(c + outChanOff) * HW;
    const float* wc = w + c * 9;

    __shared__ float sm[DTY + 2][136];

    const int tid = threadIdx.x;
    const float4 z4 = make_float4(0.f, 0.f, 0.f, 0.f);
    for (int s = tid; s < (DTY + 2) * 34; s += 256) {
        const int r = s / 34;
        const int q = s - r * 34;
        const int gy = y0 - 1 + r;
        if (q < 32) {
            float4 v = (gy >= 0 && gy < HH) ? *(const float4*)(ip + gy * WW + q * 4) : z4;
            *(float4*)&sm[r][4 + q * 4] = v;
        } else if (q == 32) {
            sm[r][3] = 0.f;
        } else {
            sm[r][4 + WW] = 0.f;
        }
    }
    __syncthreads();

    const float w00 = wc[0], w01 = wc[1], w02 = wc[2];
    const float w10 = wc[3], w11 = wc[4], w12 = wc[5];
    const float w20 = wc[6], w21 = wc[7], w22 = wc[8];

    float s2 = 0.f;
#pragma unroll
    for (int i = 0; i < (DTY * 32) / 256; i++) {
        const int oid = tid + i * 256;
        const int y = oid >> 5;
        const int xq = oid & 31;
        float o0 = 0.f, o1 = 0.f, o2 = 0.f, o3 = 0.f;
#pragma unroll
        for (int r = 0; r < 3; r++) {
            const float wr0 = (r == 0) ? w00 : (r == 1) ? w10 : w20;
            const float wr1 = (r == 0) ? w01 : (r == 1) ? w11 : w21;
            const float wr2 = (r == 0) ? w02 : (r == 1) ? w12 : w22;
            const float4 cc = *(const float4*)&sm[y + r][4 + xq * 4];
            const float l  = sm[y + r][3 + xq * 4];
            const float rr = sm[y + r][8 + xq * 4];
            o0 += l    * wr0 + cc.x * wr1 + cc.y * wr2;
            o1 += cc.x * wr0 + cc.y * wr1 + cc.z * wr2;
            o2 += cc.y * wr0 + cc.z * wr1 + cc.w * wr2;
            o3 += cc.z * wr0 + cc.w * wr1 + rr   * wr2;
        }
        if (cvtOut) {
            uint4 o = make_uint4(f2tf32(o0), f2tf32(o1), f2tf32(o2), f2tf32(o3));
            *(uint4*)((uint32_t*)out + oofs + (y0 + y) * WW + xq * 4) = o;
        } else {
            *(float4*)((float*)out + oofs + (y0 + y) * WW + xq * 4) =
                make_float4(o0, o1, o2, o3);
        }
        s2 += o0 * o0 + o1 * o1 + o2 * o2 + o3 * o3;
    }

    if (nrm) {
#pragma unroll
        for (int off = 16; off > 0; off >>= 1)
            s2 += __shfl_xor_sync(0xffffffff, s2, off);
        __shared__ float wred[8];
        if ((tid & 31) == 0) wred[tid >> 5] = s2;
        __syncthreads();
        if (tid == 0) {
            float tot = 0.f;
#pragma unroll
            for (int ww2 = 0; ww2 < 8; ww2++) tot += wred[ww2];
            atomicAdd(&nrm[b * CDIM + c], tot);
        }
    }
}

__global__ void zero_kernel()
{
    int i = blockIdx.x * blockDim.x + threadIdx.x;
    if (i < BATCH * HEADS * CH * CH) g_attn[i] = 0.f;
    if (i < BATCH * CDIM) { g_nk[i] = 0.f; g_nq[i] = 0.f; }
}

// ---------------------------------------------------------------------------
// attn_raw[bh][c][d] += sum_n q[c][n]*k[d][n]
// ---------------------------------------------------------------------------
#define NSPLIT 16
__global__ void attn_score_kernel(const float* __restrict__ q, const float* __restrict__ k)
{
    const int bh = blockIdx.x;
    const int sp = blockIdx.y;
    const int b = bh >> 3, h = bh & 7;
    const float* qp = q + ((size_t)b * CDIM + h * CH) * HW;
    const float* kp = k + ((size_t)b * CDIM + h * CH) * HW;

    __shared__ float qs[CH][36];
    __shared__ float ks[CH][36];

    const int tid = threadIdx.x;
    const int tx = tid % 16, ty = tid / 16;
    const int c0 = ty * 3, d0 = tx * 3;

    float acc[3][3] = {{0.f}};
    const int perSplit = HW / NSPLIT;
    const int base = sp * perSplit;

    for (int t0 = 0; t0 < perSplit; t0 += 32) {
        for (int i = tid; i < CH * 8; i += 256) {
            int cc = i >> 3, kq = i & 7;
            float4 vq = *(const float4*)(qp + (size_t)cc * HW + base + t0 + kq * 4);
            float4 vk = *(const float4*)(kp + (size_t)cc * HW + base + t0 + kq * 4);
            *(float4*)&qs[cc][kq * 4] = vq;
            *(float4*)&ks[cc][kq * 4] = vk;
        }
        __syncthreads();
#pragma unroll
        for (int kk = 0; kk < 32; kk++) {
            float a0 = qs[c0 + 0][kk], a1 = qs[c0 + 1][kk], a2 = qs[c0 + 2][kk];
            float e0 = ks[d0 + 0][kk], e1 = ks[d0 + 1][kk], e2 = ks[d0 + 2][kk];
            acc[0][0] += a0 * e0; acc[0][1] += a0 * e1; acc[0][2] += a0 * e2;
            acc[1][0] += a1 * e0; acc[1][1] += a1 * e1; acc[1][2] += a1 * e2;
            acc[2][0] += a2 * e0; acc[2][1] += a2 * e1; acc[2][2] += a2 * e2;
        }
        __syncthreads();
    }

    float* ap = g_attn + (size_t)bh * CH * CH;
#pragma unroll
    for (int i = 0; i < 3; i++)
#pragma unroll
        for (int j = 0; j < 3; j++)
            atomicAdd(&ap[(c0 + i) * CH + d0 + j], acc[i][j]);
}

// ---------------------------------------------------------------------------
// Softmax; nq/nk hold raw sum-of-squares
// ---------------------------------------------------------------------------
__global__ void softmax_kernel(const float* __restrict__ nq, const float* __restrict__ nk,
                               const float* __restrict__ temp)
{
    const int r = blockIdx.x;
    const int bh = r / CH, c = r % CH;
    const int b = bh >> 3, h = bh & 7;
    const int lane = threadIdx.x;

    float* row = g_attn + (size_t)bh * CH * CH + (size_t)c * CH;
    const float iq = 1.f / fmaxf(sqrtf(nq[b * CDIM + h * CH + c]), 1e-12f);
    const float tp = temp[h];

    const float ik0 = 1.f / fmaxf(sqrtf(nk[b * CDIM + h * CH + lane]), 1e-12f);
    float l0 = row[lane] * iq * ik0 * tp;
    float l1 = -INFINITY;
    if (lane < CH - 32) {
        const float ik1 = 1.f / fmaxf(sqrtf(nk[b * CDIM + h * CH + lane + 32]), 1e-12f);
        l1 = row[lane + 32] * iq * ik1 * tp;
    }

    float m = fmaxf(l0, l1);
#pragma unroll
    for (int off = 16; off > 0; off >>= 1)
        m = fmaxf(m, __shfl_xor_sync(0xffffffff, m, off));

    float e0 = expf(l0 - m);
    float e1 = (lane < CH - 32) ? expf(l1 - m) : 0.f;
    float s = e0 + e1;
#pragma unroll
    for (int off = 16; off > 0; off >>= 1)
        s += __shfl_xor_sync(0xffffffff, s, off);

    float rs = 1.f / s;
    row[lane] = e0 * rs;
    if (lane < CH - 32) row[lane + 32] = e1 * rs;
}

// ---------------------------------------------------------------------------
// out[bh][c][p] = sum_d attn[bh][c][d] * v[bh][d][p]
// ---------------------------------------------------------------------------
__global__ __launch_bounds__(128)
void attn_out_kernel(const float* __restrict__ v, float* __restrict__ out)
{
    const int bh = blockIdx.y;
    const int b = bh >> 3, h = bh & 7;
    const int p = blockIdx.x * blockDim.x + threadIdx.x;

    __shared__ float as[CH][CH];
    for (int i = threadIdx.x; i < CH * CH; i += blockDim.x)
        as[i / CH][i % CH] = g_attn[(size_t)bh * CH * CH + i];
    __syncthreads();

    const float* vp = v + ((size_t)b * CDIM + h * CH) * HW;
    float*       op = out + ((size_t)b * CDIM + h * CH) * HW;

    float vr[CH];
#pragma unroll
    for (int d = 0; d < CH; d++) vr[d] = vp[(size_t)d * HW + p];

#pragma unroll
    for (int c = 0; c < CH; c++) {
        float s = 0.f;
#pragma unroll
        for (int d = 0; d < CH; d++) s += as[c][d] * vr[d];
        op[(size_t)c * HW + p] = s;
    }
}

// ---------------------------------------------------------------------------
// Host launcher
// ---------------------------------------------------------------------------
extern "C" void kernel_launch(void* const* d_in, const int* in_sizes, int n_in,
                              void* d_out, int out_size)
{
    const float* x      = (const float*)d_in[0];
    const float* t      = (const float*)d_in[1];
    const float* w_q    = (const float*)d_in[2];
    const float* w_q_dw = (const float*)d_in[3];
    const float* w_qT   = (const float*)d_in[4];
    const float* w_qT_dw= (const float*)d_in[5];
    const float* w_qcat = (const float*)d_in[6];
    const float* w_k    = (const float*)d_in[7];
    const float* w_k_dw = (const float*)d_in[8];
    const float* w_v    = (const float*)d_in[9];
    const float* w_v_dw = (const float*)d_in[10];
    const float* temp   = (const float*)d_in[11];
    float* out = (float*)d_out;

    float *p_qkv, *p_tmp, *p_k, *p_v, *p_q, *p_nq, *p_nk;
    uint32_t *p_wtf, *p_xtf, *p_ttf, *p_cat;
    cudaGetSymbolAddress((void**)&p_qkv, g_qkv);
    cudaGetSymbolAddress((void**)&p_tmp, g_tmp);
    cudaGetSymbolAddress((void**)&p_cat, g_cat);
    cudaGetSymbolAddress((void**)&p_k,   g_k);
    cudaGetSymbolAddress((void**)&p_v,   g_v);
    cudaGetSymbolAddress((void**)&p_q,   g_q);
    cudaGetSymbolAddress((void**)&p_nq,  g_nq);
    cudaGetSymbolAddress((void**)&p_nk,  g_nk);
    cudaGetSymbolAddress((void**)&p_wtf, g_wtf);
    cudaGetSymbolAddress((void**)&p_xtf, g_xtf);
    cudaGetSymbolAddress((void**)&p_ttf, g_ttf);

    uint32_t* wqkv_t  = p_wtf;               // [wq; wk; wv] 3*WSZ
    uint32_t* wqT_t   = p_wtf + 3 * WSZ;
    uint32_t* wqcat_t = p_wtf + 4 * WSZ;

    const int gemmSmem = SMEM_FLOATS * 4;
    static int smemSet = 0;
    if (!smemSet) {
        cudaFuncSetAttribute(tgemm_kernel,
                             cudaFuncAttributeMaxDynamicSharedMemorySize, gemmSmem);
        smemSet = 1;
    }

    const dim3 gemmGridQKV(3 * CDIM / BM, HW / BN, BATCH);  // 9 x 128 x 4
    const dim3 gemmGrid(CDIM / BM, HW / BN, BATCH);         // 3 x 128 x 4
    const dim3 dwGrid(HH / DTY, CDIM, BATCH);
    const size_t bsQKV = (size_t)3 * CDIM * HW;
    const size_t bsIn  = (size_t)CDIM * HW;
    const size_t bsCat = (size_t)2 * CDIM * HW;
    const int actN4 = BATCH * CDIM * HW / 4;

    // pre-conversions
    cvtw_kernel<<<(WSZ + 255) / 256, 256>>>(w_q,  wqkv_t,           WSZ);
    cvtw_kernel<<<(WSZ + 255) / 256, 256>>>(w_k,  wqkv_t + WSZ,     WSZ);
    cvtw_kernel<<<(WSZ + 255) / 256, 256>>>(w_v,  wqkv_t + 2 * WSZ, WSZ);
    cvtw_kernel<<<(WSZ + 255) / 256, 256>>>(w_qT, wqT_t,            WSZ);
    cvtw_kernel<<<(2 * WSZ + 255) / 256, 256>>>(w_qcat, wqcat_t, 2 * WSZ);
    cvtx_kernel<<<(actN4 + 255) / 256, 256>>>((const float4*)x, (uint4*)p_xtf, actN4);
    cvtx_kernel<<<(actN4 + 255) / 256, 256>>>((const float4*)t, (uint4*)p_ttf, actN4);
    zero_kernel<<<(BATCH * HEADS * CH * CH + 255) / 256, 256>>>();

    // fused q/k/v pointwise GEMM
    tgemm_kernel<<<gemmGridQKV, 256, gemmSmem>>>(wqkv_t, p_xtf, p_qkv,
                                                 3 * CDIM, HW, CDIM, nullptr);
    // qT pointwise GEMM
    tgemm_kernel<<<gemmGrid, 256, gemmSmem>>>(wqT_t, p_ttf, p_tmp,
                                              CDIM, HW, CDIM, nullptr);

    // depthwise convs
    dw3x3_kernel<<<dwGrid, 256>>>(p_qkv, w_q_dw, p_cat, bsQKV, 0, bsCat, 0,
                                  nullptr, 1);
    dw3x3_kernel<<<dwGrid, 256>>>(p_tmp, w_qT_dw, p_cat, bsIn, 0, bsCat, CDIM,
                                  nullptr, 1);
    dw3x3_kernel<<<dwGrid, 256>>>(p_qkv, w_k_dw, p_k, bsQKV, CDIM, bsIn, 0,
                                  p_nk, 0);
    dw3x3_kernel<<<dwGrid, 256>>>(p_qkv, w_v_dw, p_v, bsQKV, 2 * CDIM, bsIn, 0,
                                  nullptr, 0);

    // q = pw(concat): K = 768, fused q-norm accumulation
    tgemm_kernel<<<gemmGrid, 256, gemmSmem>>>(wqcat_t, p_cat, p_q,
                                              CDIM, HW, 2 * CDIM, p_nq);

    attn_score_kernel<<<dim3(BATCH * HEADS, NSPLIT), 256>>>(p_q, p_k);
    softmax_kernel<<<BATCH * HEADS * CH, 32>>>(p_nq, p_nk, temp);

    attn_out_kernel<<<dim3(HW / 128, BATCH * HEADS), 128>>>(p_v, out);
}